// round 1
// baseline (speedup 1.0000x reference)
#include <cuda_runtime.h>
#include <math.h>

// Problem constants
#define SEQ   128
#define BATCH 32
#define HDIM  1024
#define EDIM  1024
#define VDIM  32000
#define MROWS (SEQ*BATCH)   // 4096
#define KSPLIT 8

// ---------------------------------------------------------------------------
// Device scratch (no allocations allowed)
// ---------------------------------------------------------------------------
__device__ float g_embeds[MROWS*EDIM];          // 16 MB  [S,B,E]
__device__ float g_xi[MROWS*HDIM];              // 16 MB  gate-i preacts (per layer, reused)
__device__ float g_xf[MROWS*HDIM];              // 16 MB
__device__ float g_seq1[MROWS*HDIM];            // 16 MB  layer-1 outputs
__device__ float g_seq2[MROWS*HDIM];            // 16 MB  layer-2 outputs
__device__ float g_lat[2][BATCH*HDIM];          // ping-pong latent
__device__ float g_part[KSPLIT*BATCH*2*HDIM];   // split-K partials [ks][b][2048]

// ---------------------------------------------------------------------------
// Embedding gather: out[sb, :] = emb[word[sb], :]
// ---------------------------------------------------------------------------
__global__ void __launch_bounds__(256) gather_kernel(
    const int* __restrict__ word, const float* __restrict__ emb,
    float* __restrict__ out)
{
    int sb = blockIdx.x;                 // 0..4095
    int w = word[sb];
    const float4* src = (const float4*)(emb + (size_t)w * EDIM);
    float4* dst = (float4*)(out + (size_t)sb * EDIM);
    #pragma unroll
    for (int i = threadIdx.x; i < EDIM/4; i += 256)
        dst[i] = src[i];
}

// ---------------------------------------------------------------------------
// Simple copy kernel (latent init)
// ---------------------------------------------------------------------------
__global__ void copy_kernel(const float* __restrict__ src, float* __restrict__ dst, int n)
{
    int i = blockIdx.x * blockDim.x + threadIdx.x;
    if (i < n) dst[i] = src[i];
}

// ---------------------------------------------------------------------------
// SGEMM (NT): C[M,N] = A[M,K] @ B[N,K]^T + bias[N]
// A, B, C row-major. M,N multiples of 128, K multiple of 8, N multiple of 4.
// 128x128 block tile, 8x8 per-thread tile, 256 threads.
// ---------------------------------------------------------------------------
__global__ void __launch_bounds__(256) sgemm_nt_kernel(
    const float* __restrict__ A, const float* __restrict__ B,
    const float* __restrict__ bias, float* __restrict__ C,
    int M, int N, int K)
{
    const int BM = 128, BN = 128, BK = 8;
    __shared__ float As[BK][BM+4];
    __shared__ float Bs[BK][BN+4];

    int tid = threadIdx.x;
    int bm = blockIdx.y * BM;
    int bn = blockIdx.x * BN;
    int tx = tid & 15;       // 0..15 -> n
    int ty = tid >> 4;       // 0..15 -> m

    float acc[8][8];
    #pragma unroll
    for (int i = 0; i < 8; i++)
        #pragma unroll
        for (int j = 0; j < 8; j++) acc[i][j] = 0.f;

    int lrow = tid >> 1;          // 0..127
    int lcol = (tid & 1) * 4;     // 0 or 4
    const float* Ap = A + (size_t)(bm + lrow) * K + lcol;
    const float* Bp = B + (size_t)(bn + lrow) * K + lcol;

    for (int k0 = 0; k0 < K; k0 += BK) {
        float4 av = *(const float4*)(Ap + k0);
        float4 bv = *(const float4*)(Bp + k0);
        As[lcol+0][lrow] = av.x; As[lcol+1][lrow] = av.y;
        As[lcol+2][lrow] = av.z; As[lcol+3][lrow] = av.w;
        Bs[lcol+0][lrow] = bv.x; Bs[lcol+1][lrow] = bv.y;
        Bs[lcol+2][lrow] = bv.z; Bs[lcol+3][lrow] = bv.w;
        __syncthreads();

        #pragma unroll
        for (int k = 0; k < BK; k++) {
            float a[8], b[8];
            *(float4*)&a[0] = *(const float4*)&As[k][ty*8];
            *(float4*)&a[4] = *(const float4*)&As[k][ty*8+4];
            *(float4*)&b[0] = *(const float4*)&Bs[k][tx*8];
            *(float4*)&b[4] = *(const float4*)&Bs[k][tx*8+4];
            #pragma unroll
            for (int i = 0; i < 8; i++)
                #pragma unroll
                for (int j = 0; j < 8; j++)
                    acc[i][j] += a[i] * b[j];
        }
        __syncthreads();
    }

    #pragma unroll
    for (int i = 0; i < 8; i++) {
        size_t row = (size_t)(bm + ty*8 + i);
        #pragma unroll
        for (int j = 0; j < 8; j += 4) {
            int col = bn + tx*8 + j;
            float4 v;
            v.x = acc[i][j+0] + bias[col+0];
            v.y = acc[i][j+1] + bias[col+1];
            v.z = acc[i][j+2] + bias[col+2];
            v.w = acc[i][j+3] + bias[col+3];
            *(float4*)&C[row * (size_t)N + col] = v;
        }
    }
}

// ---------------------------------------------------------------------------
// Recurrence step GEMM (split-K): partial[ks][b][g2] = sum_{k in slice}
//   lat[b,k] * W[g2][k]   where g2<1024 -> Whi row g2, else Whf row g2-1024.
// grid = (16 g-tiles of 128, 8 k-slices of 128), 256 threads.
// Per-thread 4(b) x 4(g) register tile.
// ---------------------------------------------------------------------------
__global__ void __launch_bounds__(256) step_gemm_kernel(
    const float* __restrict__ lat,   // [B,H]
    const float* __restrict__ Wi,    // [H,H]
    const float* __restrict__ Wf,    // [H,H]
    float* __restrict__ part)        // [KSPLIT][B][2H]
{
    __shared__ float lat_s[8][36];   // [k][b], padded (stride 144B, 16B aligned)
    __shared__ float w_s[8][132];    // [k][g], padded (stride 528B, 16B aligned)

    int tid = threadIdx.x;
    int gbase = blockIdx.x * 128;        // 0..2047
    int k0 = blockIdx.y * 128;           // k-slice base

    const float* W = (gbase < HDIM) ? Wi : Wf;
    int grow = (gbase < HDIM) ? gbase : (gbase - HDIM);

    float acc[4][4];
    #pragma unroll
    for (int i = 0; i < 4; i++)
        #pragma unroll
        for (int j = 0; j < 4; j++) acc[i][j] = 0.f;

    int bq = (tid >> 5) * 4;     // batch base (0..28)
    int gq = (tid & 31) * 4;     // g base within tile (0..124)

    for (int kk = 0; kk < 128; kk += 8) {
        // load latent chunk: 32 b x 8 k
        {
            int b = tid >> 3, k = tid & 7;
            lat_s[k][b] = lat[b * HDIM + k0 + kk + k];
        }
        // load W chunk: 128 g x 8 k (float4 over k)
        {
            int g = tid >> 1, kq = (tid & 1) * 4;
            float4 wv = *(const float4*)&W[(size_t)(grow + g) * HDIM + k0 + kk + kq];
            w_s[kq+0][g] = wv.x; w_s[kq+1][g] = wv.y;
            w_s[kq+2][g] = wv.z; w_s[kq+3][g] = wv.w;
        }
        __syncthreads();
        #pragma unroll
        for (int k = 0; k < 8; k++) {
            float a[4], b4[4];
            *(float4*)a  = *(const float4*)&lat_s[k][bq];
            *(float4*)b4 = *(const float4*)&w_s[k][gq];
            #pragma unroll
            for (int i = 0; i < 4; i++)
                #pragma unroll
                for (int j = 0; j < 4; j++)
                    acc[i][j] += a[i] * b4[j];
        }
        __syncthreads();
    }

    float* p = part + (size_t)(blockIdx.y * BATCH) * (2*HDIM);
    #pragma unroll
    for (int i = 0; i < 4; i++) {
        int b = bq + i;
        *(float4*)&p[b * (2*HDIM) + gbase + gq] = *(float4*)acc[i];
    }
}

// ---------------------------------------------------------------------------
// Recurrence step update: reduce split-K partials, sigmoid gates, latent update
// ---------------------------------------------------------------------------
__global__ void __launch_bounds__(256) step_update_kernel(
    const float* __restrict__ part,
    const float* __restrict__ xi_t,  // [B,H]
    const float* __restrict__ xf_t,  // [B,H]
    const float* __restrict__ x_t,   // [B,H]
    const float* __restrict__ lat_in,
    float* __restrict__ lat_out,
    float* __restrict__ seq_out,
    float* __restrict__ ig_out,      // nullable (last step of layer 2)
    float* __restrict__ fg_out,      // nullable
    float* __restrict__ lat_final)   // nullable
{
    int idx = blockIdx.x * blockDim.x + threadIdx.x;   // 0..32767
    int b = idx >> 10;      // /HDIM
    int g = idx & 1023;

    float si = 0.f, sf = 0.f;
    #pragma unroll
    for (int ks = 0; ks < KSPLIT; ks++) {
        const float* p = part + (size_t)(ks * BATCH + b) * (2*HDIM);
        si += p[g];
        sf += p[g + HDIM];
    }
    float ig = 1.f / (1.f + expf(-(si + xi_t[idx])));
    float fg = 1.f / (1.f + expf(-(sf + xf_t[idx])));
    float l = ig * x_t[idx] + fg * lat_in[idx];
    lat_out[idx] = l;
    seq_out[idx] = l;
    if (ig_out) {
        ig_out[idx] = ig;
        fg_out[idx] = fg;
        lat_final[idx] = l;
    }
}

// ---------------------------------------------------------------------------
// Host launcher
// ---------------------------------------------------------------------------
static float* sym_addr(const void* symbol)
{
    void* p = nullptr;
    cudaGetSymbolAddress(&p, symbol);
    return (float*)p;
}

extern "C" void kernel_launch(void* const* d_in, const int* in_sizes, int n_in,
                              void* d_out, int out_size)
{
    const int*   word   = (const int*)  d_in[0];
    const float* latent = (const float*)d_in[1];
    const float* emb    = (const float*)d_in[2];
    const float* h2o_w  = (const float*)d_in[3];
    const float* h2o_b  = (const float*)d_in[4];
    const float* Whi    = (const float*)d_in[5];
    const float* Wxi_w  = (const float*)d_in[6];
    const float* Wxi_b  = (const float*)d_in[7];
    const float* Whf    = (const float*)d_in[8];
    const float* Wxf_w  = (const float*)d_in[9];
    const float* Wxf_b  = (const float*)d_in[10];
    const float* Whi2   = (const float*)d_in[11];
    const float* Wxi2_w = (const float*)d_in[12];
    const float* Wxi2_b = (const float*)d_in[13];
    const float* Whf2   = (const float*)d_in[14];
    const float* Wxf2_w = (const float*)d_in[15];
    const float* Wxf2_b = (const float*)d_in[16];

    float* out_latent = (float*)d_out;                         // [1,B,H]
    float* out_logits = out_latent + BATCH*HDIM;               // [S,B,V]
    float* out_ig     = out_logits + (size_t)SEQ*BATCH*VDIM;   // [1,B,H]
    float* out_fg     = out_ig + BATCH*HDIM;                   // [1,B,H]

    float* embeds = sym_addr(g_embeds);
    float* xi     = sym_addr(g_xi);
    float* xf     = sym_addr(g_xf);
    float* seq1   = sym_addr(g_seq1);
    float* seq2   = sym_addr(g_seq2);
    float* lat    = sym_addr(g_lat);      // lat buf 0; buf 1 at +BATCH*HDIM
    float* part   = sym_addr(g_part);
    float* lat0 = lat;
    float* lat1 = lat + BATCH*HDIM;

    // 1) Embedding gather
    gather_kernel<<<MROWS, 256>>>(word, emb, embeds);

    // 2) Layer-1 input gate preactivations: xi/xf = embeds @ W^T + b
    {
        dim3 grid(HDIM/128, MROWS/128);
        sgemm_nt_kernel<<<grid, 256>>>(embeds, Wxi_w, Wxi_b, xi, MROWS, HDIM, EDIM);
        sgemm_nt_kernel<<<grid, 256>>>(embeds, Wxf_w, Wxf_b, xf, MROWS, HDIM, EDIM);
    }

    // 3) Latent init
    copy_kernel<<<(BATCH*HDIM + 255)/256, 256>>>(latent, lat0, BATCH*HDIM);

    // 4) Layer-1 recurrence
    for (int t = 0; t < SEQ; t++) {
        float* lin  = (t & 1) ? lat1 : lat0;
        float* lout = (t & 1) ? lat0 : lat1;
        step_gemm_kernel<<<dim3(16, KSPLIT), 256>>>(lin, Whi, Whf, part);
        step_update_kernel<<<128, 256>>>(part,
            xi + (size_t)t*BATCH*HDIM, xf + (size_t)t*BATCH*HDIM,
            embeds + (size_t)t*BATCH*HDIM,
            lin, lout, seq1 + (size_t)t*BATCH*HDIM,
            nullptr, nullptr, nullptr);
    }
    // after 128 steps, final latent is in lat0

    // 5) Layer-2 input gate preactivations from seq1
    {
        dim3 grid(HDIM/128, MROWS/128);
        sgemm_nt_kernel<<<grid, 256>>>(seq1, Wxi2_w, Wxi2_b, xi, MROWS, HDIM, HDIM);
        sgemm_nt_kernel<<<grid, 256>>>(seq1, Wxf2_w, Wxf2_b, xf, MROWS, HDIM, HDIM);
    }

    // 6) Layer-2 recurrence (continues ping-pong from lat0)
    for (int t = 0; t < SEQ; t++) {
        float* lin  = (t & 1) ? lat1 : lat0;
        float* lout = (t & 1) ? lat0 : lat1;
        bool last = (t == SEQ-1);
        step_gemm_kernel<<<dim3(16, KSPLIT), 256>>>(lin, Whi2, Whf2, part);
        step_update_kernel<<<128, 256>>>(part,
            xi + (size_t)t*BATCH*HDIM, xf + (size_t)t*BATCH*HDIM,
            seq1 + (size_t)t*BATCH*HDIM,
            lin, lout, seq2 + (size_t)t*BATCH*HDIM,
            last ? out_ig : nullptr,
            last ? out_fg : nullptr,
            last ? out_latent : nullptr);
    }

    // 7) Logits: seq2 @ h2o_w^T + h2o_b  -> [S*B, V]
    {
        dim3 grid(VDIM/128, MROWS/128);
        sgemm_nt_kernel<<<grid, 256>>>(seq2, h2o_w, h2o_b, out_logits, MROWS, VDIM, HDIM);
    }
}

// round 2
// speedup vs baseline: 1.0007x; 1.0007x over previous
#include <cuda_runtime.h>
#include <math.h>

// Problem constants
#define SEQ   128
#define BATCH 32
#define HDIM  1024
#define EDIM  1024
#define VDIM  32000
#define MROWS (SEQ*BATCH)   // 4096
#define KSPLIT 8

// ---------------------------------------------------------------------------
// Device scratch (no allocations allowed)
// ---------------------------------------------------------------------------
__device__ float g_embeds[MROWS*EDIM];          // 16 MB  [S,B,E]
__device__ float g_xi[MROWS*HDIM];              // 16 MB  gate-i preacts (per layer, reused)
__device__ float g_xf[MROWS*HDIM];              // 16 MB
__device__ float g_seq1[MROWS*HDIM];            // 16 MB  layer-1 outputs
__device__ float g_seq2[MROWS*HDIM];            // 16 MB  layer-2 outputs
__device__ float g_lat[2][BATCH*HDIM];          // ping-pong latent
__device__ float g_part[KSPLIT*BATCH*2*HDIM];   // split-K partials [ks][b][2048]

// ---------------------------------------------------------------------------
// Embedding gather: out[sb, :] = emb[word[sb], :]
// ---------------------------------------------------------------------------
__global__ void __launch_bounds__(256) gather_kernel(
    const int* __restrict__ word, const float* __restrict__ emb,
    float* __restrict__ out)
{
    int sb = blockIdx.x;                 // 0..4095
    int w = word[sb];
    const float4* src = (const float4*)(emb + (size_t)w * EDIM);
    float4* dst = (float4*)(out + (size_t)sb * EDIM);
    #pragma unroll
    for (int i = threadIdx.x; i < EDIM/4; i += 256)
        dst[i] = src[i];
}

// ---------------------------------------------------------------------------
// Simple copy kernel (latent init)
// ---------------------------------------------------------------------------
__global__ void copy_kernel(const float* __restrict__ src, float* __restrict__ dst, int n)
{
    int i = blockIdx.x * blockDim.x + threadIdx.x;
    if (i < n) dst[i] = src[i];
}

// ---------------------------------------------------------------------------
// SGEMM (NT): C[M,N] = A[M,K] @ B[N,K]^T + bias[N]
// A, B, C row-major. M,N multiples of 128, K multiple of 8, N multiple of 4.
// 128x128 block tile, 8x8 per-thread tile, 256 threads.
// ---------------------------------------------------------------------------
__global__ void __launch_bounds__(256) sgemm_nt_kernel(
    const float* __restrict__ A, const float* __restrict__ B,
    const float* __restrict__ bias, float* __restrict__ C,
    int M, int N, int K)
{
    const int BM = 128, BN = 128, BK = 8;
    __shared__ float As[BK][BM+4];
    __shared__ float Bs[BK][BN+4];

    int tid = threadIdx.x;
    int bm = blockIdx.y * BM;
    int bn = blockIdx.x * BN;
    int tx = tid & 15;       // 0..15 -> n
    int ty = tid >> 4;       // 0..15 -> m

    float acc[8][8];
    #pragma unroll
    for (int i = 0; i < 8; i++)
        #pragma unroll
        for (int j = 0; j < 8; j++) acc[i][j] = 0.f;

    int lrow = tid >> 1;          // 0..127
    int lcol = (tid & 1) * 4;     // 0 or 4
    const float* Ap = A + (size_t)(bm + lrow) * K + lcol;
    const float* Bp = B + (size_t)(bn + lrow) * K + lcol;

    for (int k0 = 0; k0 < K; k0 += BK) {
        float4 av = *(const float4*)(Ap + k0);
        float4 bv = *(const float4*)(Bp + k0);
        As[lcol+0][lrow] = av.x; As[lcol+1][lrow] = av.y;
        As[lcol+2][lrow] = av.z; As[lcol+3][lrow] = av.w;
        Bs[lcol+0][lrow] = bv.x; Bs[lcol+1][lrow] = bv.y;
        Bs[lcol+2][lrow] = bv.z; Bs[lcol+3][lrow] = bv.w;
        __syncthreads();

        #pragma unroll
        for (int k = 0; k < BK; k++) {
            float a[8], b[8];
            *(float4*)&a[0] = *(const float4*)&As[k][ty*8];
            *(float4*)&a[4] = *(const float4*)&As[k][ty*8+4];
            *(float4*)&b[0] = *(const float4*)&Bs[k][tx*8];
            *(float4*)&b[4] = *(const float4*)&Bs[k][tx*8+4];
            #pragma unroll
            for (int i = 0; i < 8; i++)
                #pragma unroll
                for (int j = 0; j < 8; j++)
                    acc[i][j] += a[i] * b[j];
        }
        __syncthreads();
    }

    #pragma unroll
    for (int i = 0; i < 8; i++) {
        size_t row = (size_t)(bm + ty*8 + i);
        #pragma unroll
        for (int j = 0; j < 8; j += 4) {
            int col = bn + tx*8 + j;
            float4 v;
            v.x = acc[i][j+0] + bias[col+0];
            v.y = acc[i][j+1] + bias[col+1];
            v.z = acc[i][j+2] + bias[col+2];
            v.w = acc[i][j+3] + bias[col+3];
            *(float4*)&C[row * (size_t)N + col] = v;
        }
    }
}

// ---------------------------------------------------------------------------
// Recurrence step GEMM (split-K): partial[ks][b][g2] = sum_{k in slice}
//   lat[b,k] * W[g2][k]   where g2<1024 -> Whi row g2, else Whf row g2-1024.
// grid = (16 g-tiles of 128, 8 k-slices of 128), 256 threads.
// Per-thread 4(b) x 4(g) register tile.
// ---------------------------------------------------------------------------
__global__ void __launch_bounds__(256) step_gemm_kernel(
    const float* __restrict__ lat,   // [B,H]
    const float* __restrict__ Wi,    // [H,H]
    const float* __restrict__ Wf,    // [H,H]
    float* __restrict__ part)        // [KSPLIT][B][2H]
{
    __shared__ float lat_s[8][36];   // [k][b], padded (stride 144B, 16B aligned)
    __shared__ float w_s[8][132];    // [k][g], padded (stride 528B, 16B aligned)

    int tid = threadIdx.x;
    int gbase = blockIdx.x * 128;        // 0..2047
    int k0 = blockIdx.y * 128;           // k-slice base

    const float* W = (gbase < HDIM) ? Wi : Wf;
    int grow = (gbase < HDIM) ? gbase : (gbase - HDIM);

    float acc[4][4];
    #pragma unroll
    for (int i = 0; i < 4; i++)
        #pragma unroll
        for (int j = 0; j < 4; j++) acc[i][j] = 0.f;

    int bq = (tid >> 5) * 4;     // batch base (0..28)
    int gq = (tid & 31) * 4;     // g base within tile (0..124)

    for (int kk = 0; kk < 128; kk += 8) {
        // load latent chunk: 32 b x 8 k
        {
            int b = tid >> 3, k = tid & 7;
            lat_s[k][b] = lat[b * HDIM + k0 + kk + k];
        }
        // load W chunk: 128 g x 8 k (float4 over k)
        {
            int g = tid >> 1, kq = (tid & 1) * 4;
            float4 wv = *(const float4*)&W[(size_t)(grow + g) * HDIM + k0 + kk + kq];
            w_s[kq+0][g] = wv.x; w_s[kq+1][g] = wv.y;
            w_s[kq+2][g] = wv.z; w_s[kq+3][g] = wv.w;
        }
        __syncthreads();
        #pragma unroll
        for (int k = 0; k < 8; k++) {
            float a[4], b4[4];
            *(float4*)a  = *(const float4*)&lat_s[k][bq];
            *(float4*)b4 = *(const float4*)&w_s[k][gq];
            #pragma unroll
            for (int i = 0; i < 4; i++)
                #pragma unroll
                for (int j = 0; j < 4; j++)
                    acc[i][j] += a[i] * b4[j];
        }
        __syncthreads();
    }

    float* p = part + (size_t)(blockIdx.y * BATCH) * (2*HDIM);
    #pragma unroll
    for (int i = 0; i < 4; i++) {
        int b = bq + i;
        *(float4*)&p[b * (2*HDIM) + gbase + gq] = *(float4*)acc[i];
    }
}

// ---------------------------------------------------------------------------
// Recurrence step update: reduce split-K partials, sigmoid gates, latent update
// ---------------------------------------------------------------------------
__global__ void __launch_bounds__(256) step_update_kernel(
    const float* __restrict__ part,
    const float* __restrict__ xi_t,  // [B,H]
    const float* __restrict__ xf_t,  // [B,H]
    const float* __restrict__ x_t,   // [B,H]
    const float* __restrict__ lat_in,
    float* __restrict__ lat_out,
    float* __restrict__ seq_out,
    float* __restrict__ ig_out,      // nullable (last step of layer 2)
    float* __restrict__ fg_out,      // nullable
    float* __restrict__ lat_final)   // nullable
{
    int idx = blockIdx.x * blockDim.x + threadIdx.x;   // 0..32767
    int b = idx >> 10;      // /HDIM
    int g = idx & 1023;

    float si = 0.f, sf = 0.f;
    #pragma unroll
    for (int ks = 0; ks < KSPLIT; ks++) {
        const float* p = part + (size_t)(ks * BATCH + b) * (2*HDIM);
        si += p[g];
        sf += p[g + HDIM];
    }
    float ig = 1.f / (1.f + expf(-(si + xi_t[idx])));
    float fg = 1.f / (1.f + expf(-(sf + xf_t[idx])));
    float l = ig * x_t[idx] + fg * lat_in[idx];
    lat_out[idx] = l;
    seq_out[idx] = l;
    if (ig_out) {
        ig_out[idx] = ig;
        fg_out[idx] = fg;
        lat_final[idx] = l;
    }
}

// ---------------------------------------------------------------------------
// Host launcher
// ---------------------------------------------------------------------------
static float* sym_addr(const void* symbol)
{
    void* p = nullptr;
    cudaGetSymbolAddress(&p, symbol);
    return (float*)p;
}

extern "C" void kernel_launch(void* const* d_in, const int* in_sizes, int n_in,
                              void* d_out, int out_size)
{
    const int*   word   = (const int*)  d_in[0];
    const float* latent = (const float*)d_in[1];
    const float* emb    = (const float*)d_in[2];
    const float* h2o_w  = (const float*)d_in[3];
    const float* h2o_b  = (const float*)d_in[4];
    const float* Whi    = (const float*)d_in[5];
    const float* Wxi_w  = (const float*)d_in[6];
    const float* Wxi_b  = (const float*)d_in[7];
    const float* Whf    = (const float*)d_in[8];
    const float* Wxf_w  = (const float*)d_in[9];
    const float* Wxf_b  = (const float*)d_in[10];
    const float* Whi2   = (const float*)d_in[11];
    const float* Wxi2_w = (const float*)d_in[12];
    const float* Wxi2_b = (const float*)d_in[13];
    const float* Whf2   = (const float*)d_in[14];
    const float* Wxf2_w = (const float*)d_in[15];
    const float* Wxf2_b = (const float*)d_in[16];

    float* out_latent = (float*)d_out;                         // [1,B,H]
    float* out_logits = out_latent + BATCH*HDIM;               // [S,B,V]
    float* out_ig     = out_logits + (size_t)SEQ*BATCH*VDIM;   // [1,B,H]
    float* out_fg     = out_ig + BATCH*HDIM;                   // [1,B,H]

    float* embeds = sym_addr(g_embeds);
    float* xi     = sym_addr(g_xi);
    float* xf     = sym_addr(g_xf);
    float* seq1   = sym_addr(g_seq1);
    float* seq2   = sym_addr(g_seq2);
    float* lat    = sym_addr(g_lat);      // lat buf 0; buf 1 at +BATCH*HDIM
    float* part   = sym_addr(g_part);
    float* lat0 = lat;
    float* lat1 = lat + BATCH*HDIM;

    // 1) Embedding gather
    gather_kernel<<<MROWS, 256>>>(word, emb, embeds);

    // 2) Layer-1 input gate preactivations: xi/xf = embeds @ W^T + b
    {
        dim3 grid(HDIM/128, MROWS/128);
        sgemm_nt_kernel<<<grid, 256>>>(embeds, Wxi_w, Wxi_b, xi, MROWS, HDIM, EDIM);
        sgemm_nt_kernel<<<grid, 256>>>(embeds, Wxf_w, Wxf_b, xf, MROWS, HDIM, EDIM);
    }

    // 3) Latent init
    copy_kernel<<<(BATCH*HDIM + 255)/256, 256>>>(latent, lat0, BATCH*HDIM);

    // 4) Layer-1 recurrence
    for (int t = 0; t < SEQ; t++) {
        float* lin  = (t & 1) ? lat1 : lat0;
        float* lout = (t & 1) ? lat0 : lat1;
        step_gemm_kernel<<<dim3(16, KSPLIT), 256>>>(lin, Whi, Whf, part);
        step_update_kernel<<<128, 256>>>(part,
            xi + (size_t)t*BATCH*HDIM, xf + (size_t)t*BATCH*HDIM,
            embeds + (size_t)t*BATCH*HDIM,
            lin, lout, seq1 + (size_t)t*BATCH*HDIM,
            nullptr, nullptr, nullptr);
    }
    // after 128 steps, final latent is in lat0

    // 5) Layer-2 input gate preactivations from seq1
    {
        dim3 grid(HDIM/128, MROWS/128);
        sgemm_nt_kernel<<<grid, 256>>>(seq1, Wxi2_w, Wxi2_b, xi, MROWS, HDIM, HDIM);
        sgemm_nt_kernel<<<grid, 256>>>(seq1, Wxf2_w, Wxf2_b, xf, MROWS, HDIM, HDIM);
    }

    // 6) Layer-2 recurrence (continues ping-pong from lat0)
    for (int t = 0; t < SEQ; t++) {
        float* lin  = (t & 1) ? lat1 : lat0;
        float* lout = (t & 1) ? lat0 : lat1;
        bool last = (t == SEQ-1);
        step_gemm_kernel<<<dim3(16, KSPLIT), 256>>>(lin, Whi2, Whf2, part);
        step_update_kernel<<<128, 256>>>(part,
            xi + (size_t)t*BATCH*HDIM, xf + (size_t)t*BATCH*HDIM,
            seq1 + (size_t)t*BATCH*HDIM,
            lin, lout, seq2 + (size_t)t*BATCH*HDIM,
            last ? out_ig : nullptr,
            last ? out_fg : nullptr,
            last ? out_latent : nullptr);
    }

    // 7) Logits: seq2 @ h2o_w^T + h2o_b  -> [S*B, V]
    {
        dim3 grid(VDIM/128, MROWS/128);
        sgemm_nt_kernel<<<grid, 256>>>(seq2, h2o_w, h2o_b, out_logits, MROWS, VDIM, HDIM);
    }
}

// round 5
// speedup vs baseline: 1.0010x; 1.0003x over previous
#include <cuda_runtime.h>
#include <math.h>

// Problem constants
#define SEQ   128
#define BATCH 32
#define HDIM  1024
#define EDIM  1024
#define VDIM  32000
#define MROWS (SEQ*BATCH)   // 4096
#define KSPLIT 8

// ---------------------------------------------------------------------------
// Device scratch (no allocations allowed)
// ---------------------------------------------------------------------------
__device__ float g_embeds[MROWS*EDIM];          // 16 MB  [S,B,E]
__device__ float g_xi[MROWS*HDIM];              // 16 MB  gate-i preacts (per layer, reused)
__device__ float g_xf[MROWS*HDIM];              // 16 MB
__device__ float g_seq1[MROWS*HDIM];            // 16 MB  layer-1 outputs
__device__ float g_seq2[MROWS*HDIM];            // 16 MB  layer-2 outputs
__device__ float g_lat[2][BATCH*HDIM];          // ping-pong latent
__device__ float g_part[KSPLIT*BATCH*2*HDIM];   // split-K partials [ks][b][2048]

// ---------------------------------------------------------------------------
// Embedding gather: out[sb, :] = emb[word[sb], :]
// ---------------------------------------------------------------------------
__global__ void __launch_bounds__(256) gather_kernel(
    const int* __restrict__ word, const float* __restrict__ emb,
    float* __restrict__ out)
{
    int sb = blockIdx.x;                 // 0..4095
    int w = word[sb];
    const float4* src = (const float4*)(emb + (size_t)w * EDIM);
    float4* dst = (float4*)(out + (size_t)sb * EDIM);
    #pragma unroll
    for (int i = threadIdx.x; i < EDIM/4; i += 256)
        dst[i] = src[i];
}

// ---------------------------------------------------------------------------
// Simple copy kernel (latent init)
// ---------------------------------------------------------------------------
__global__ void copy_kernel(const float* __restrict__ src, float* __restrict__ dst, int n)
{
    int i = blockIdx.x * blockDim.x + threadIdx.x;
    if (i < n) dst[i] = src[i];
}

// ---------------------------------------------------------------------------
// SGEMM (NT): C[M,N] = A[M,K] @ B[N,K]^T + bias[N]
// A, B, C row-major. M,N multiples of 128, K multiple of 8, N multiple of 4.
// 128x128 block tile, 8x8 per-thread tile, 256 threads.
// ---------------------------------------------------------------------------
__global__ void __launch_bounds__(256) sgemm_nt_kernel(
    const float* __restrict__ A, const float* __restrict__ B,
    const float* __restrict__ bias, float* __restrict__ C,
    int M, int N, int K)
{
    const int BM = 128, BN = 128, BK = 8;
    __shared__ float As[BK][BM+4];
    __shared__ float Bs[BK][BN+4];

    int tid = threadIdx.x;
    int bm = blockIdx.y * BM;
    int bn = blockIdx.x * BN;
    int tx = tid & 15;       // 0..15 -> n
    int ty = tid >> 4;       // 0..15 -> m

    float acc[8][8];
    #pragma unroll
    for (int i = 0; i < 8; i++)
        #pragma unroll
        for (int j = 0; j < 8; j++) acc[i][j] = 0.f;

    int lrow = tid >> 1;          // 0..127
    int lcol = (tid & 1) * 4;     // 0 or 4
    const float* Ap = A + (size_t)(bm + lrow) * K + lcol;
    const float* Bp = B + (size_t)(bn + lrow) * K + lcol;

    for (int k0 = 0; k0 < K; k0 += BK) {
        float4 av = *(const float4*)(Ap + k0);
        float4 bv = *(const float4*)(Bp + k0);
        As[lcol+0][lrow] = av.x; As[lcol+1][lrow] = av.y;
        As[lcol+2][lrow] = av.z; As[lcol+3][lrow] = av.w;
        Bs[lcol+0][lrow] = bv.x; Bs[lcol+1][lrow] = bv.y;
        Bs[lcol+2][lrow] = bv.z; Bs[lcol+3][lrow] = bv.w;
        __syncthreads();

        #pragma unroll
        for (int k = 0; k < BK; k++) {
            float a[8], b[8];
            *(float4*)&a[0] = *(const float4*)&As[k][ty*8];
            *(float4*)&a[4] = *(const float4*)&As[k][ty*8+4];
            *(float4*)&b[0] = *(const float4*)&Bs[k][tx*8];
            *(float4*)&b[4] = *(const float4*)&Bs[k][tx*8+4];
            #pragma unroll
            for (int i = 0; i < 8; i++)
                #pragma unroll
                for (int j = 0; j < 8; j++)
                    acc[i][j] += a[i] * b[j];
        }
        __syncthreads();
    }

    #pragma unroll
    for (int i = 0; i < 8; i++) {
        size_t row = (size_t)(bm + ty*8 + i);
        #pragma unroll
        for (int j = 0; j < 8; j += 4) {
            int col = bn + tx*8 + j;
            float4 v;
            v.x = acc[i][j+0] + bias[col+0];
            v.y = acc[i][j+1] + bias[col+1];
            v.z = acc[i][j+2] + bias[col+2];
            v.w = acc[i][j+3] + bias[col+3];
            *(float4*)&C[row * (size_t)N + col] = v;
        }
    }
}

// ---------------------------------------------------------------------------
// Recurrence step GEMM (split-K): partial[ks][b][g2] = sum_{k in slice}
//   lat[b,k] * W[g2][k]   where g2<1024 -> Whi row g2, else Whf row g2-1024.
// grid = (16 g-tiles of 128, 8 k-slices of 128), 256 threads.
// Per-thread 4(b) x 4(g) register tile.
// ---------------------------------------------------------------------------
__global__ void __launch_bounds__(256) step_gemm_kernel(
    const float* __restrict__ lat,   // [B,H]
    const float* __restrict__ Wi,    // [H,H]
    const float* __restrict__ Wf,    // [H,H]
    float* __restrict__ part)        // [KSPLIT][B][2H]
{
    __shared__ float lat_s[8][36];   // [k][b], padded (stride 144B, 16B aligned)
    __shared__ float w_s[8][132];    // [k][g], padded (stride 528B, 16B aligned)

    int tid = threadIdx.x;
    int gbase = blockIdx.x * 128;        // 0..2047
    int k0 = blockIdx.y * 128;           // k-slice base

    const float* W = (gbase < HDIM) ? Wi : Wf;
    int grow = (gbase < HDIM) ? gbase : (gbase - HDIM);

    float acc[4][4];
    #pragma unroll
    for (int i = 0; i < 4; i++)
        #pragma unroll
        for (int j = 0; j < 4; j++) acc[i][j] = 0.f;

    int bq = (tid >> 5) * 4;     // batch base (0..28)
    int gq = (tid & 31) * 4;     // g base within tile (0..124)

    for (int kk = 0; kk < 128; kk += 8) {
        // load latent chunk: 32 b x 8 k
        {
            int b = tid >> 3, k = tid & 7;
            lat_s[k][b] = lat[b * HDIM + k0 + kk + k];
        }
        // load W chunk: 128 g x 8 k (float4 over k)
        {
            int g = tid >> 1, kq = (tid & 1) * 4;
            float4 wv = *(const float4*)&W[(size_t)(grow + g) * HDIM + k0 + kk + kq];
            w_s[kq+0][g] = wv.x; w_s[kq+1][g] = wv.y;
            w_s[kq+2][g] = wv.z; w_s[kq+3][g] = wv.w;
        }
        __syncthreads();
        #pragma unroll
        for (int k = 0; k < 8; k++) {
            float a[4], b4[4];
            *(float4*)a  = *(const float4*)&lat_s[k][bq];
            *(float4*)b4 = *(const float4*)&w_s[k][gq];
            #pragma unroll
            for (int i = 0; i < 4; i++)
                #pragma unroll
                for (int j = 0; j < 4; j++)
                    acc[i][j] += a[i] * b4[j];
        }
        __syncthreads();
    }

    float* p = part + (size_t)(blockIdx.y * BATCH) * (2*HDIM);
    #pragma unroll
    for (int i = 0; i < 4; i++) {
        int b = bq + i;
        *(float4*)&p[b * (2*HDIM) + gbase + gq] = *(float4*)acc[i];
    }
}

// ---------------------------------------------------------------------------
// Recurrence step update: reduce split-K partials, sigmoid gates, latent update
// ---------------------------------------------------------------------------
__global__ void __launch_bounds__(256) step_update_kernel(
    const float* __restrict__ part,
    const float* __restrict__ xi_t,  // [B,H]
    const float* __restrict__ xf_t,  // [B,H]
    const float* __restrict__ x_t,   // [B,H]
    const float* __restrict__ lat_in,
    float* __restrict__ lat_out,
    float* __restrict__ seq_out,
    float* __restrict__ ig_out,      // nullable (last step of layer 2)
    float* __restrict__ fg_out,      // nullable
    float* __restrict__ lat_final)   // nullable
{
    int idx = blockIdx.x * blockDim.x + threadIdx.x;   // 0..32767
    int b = idx >> 10;      // /HDIM
    int g = idx & 1023;

    float si = 0.f, sf = 0.f;
    #pragma unroll
    for (int ks = 0; ks < KSPLIT; ks++) {
        const float* p = part + (size_t)(ks * BATCH + b) * (2*HDIM);
        si += p[g];
        sf += p[g + HDIM];
    }
    float ig = 1.f / (1.f + expf(-(si + xi_t[idx])));
    float fg = 1.f / (1.f + expf(-(sf + xf_t[idx])));
    float l = ig * x_t[idx] + fg * lat_in[idx];
    lat_out[idx] = l;
    seq_out[idx] = l;
    if (ig_out) {
        ig_out[idx] = ig;
        fg_out[idx] = fg;
        lat_final[idx] = l;
    }
}

// ---------------------------------------------------------------------------
// Host launcher
// ---------------------------------------------------------------------------
static float* sym_addr(const void* symbol)
{
    void* p = nullptr;
    cudaGetSymbolAddress(&p, symbol);
    return (float*)p;
}

extern "C" void kernel_launch(void* const* d_in, const int* in_sizes, int n_in,
                              void* d_out, int out_size)
{
    const int*   word   = (const int*)  d_in[0];
    const float* latent = (const float*)d_in[1];
    const float* emb    = (const float*)d_in[2];
    const float* h2o_w  = (const float*)d_in[3];
    const float* h2o_b  = (const float*)d_in[4];
    const float* Whi    = (const float*)d_in[5];
    const float* Wxi_w  = (const float*)d_in[6];
    const float* Wxi_b  = (const float*)d_in[7];
    const float* Whf    = (const float*)d_in[8];
    const float* Wxf_w  = (const float*)d_in[9];
    const float* Wxf_b  = (const float*)d_in[10];
    const float* Whi2   = (const float*)d_in[11];
    const float* Wxi2_w = (const float*)d_in[12];
    const float* Wxi2_b = (const float*)d_in[13];
    const float* Whf2   = (const float*)d_in[14];
    const float* Wxf2_w = (const float*)d_in[15];
    const float* Wxf2_b = (const float*)d_in[16];

    float* out_latent = (float*)d_out;                         // [1,B,H]
    float* out_logits = out_latent + BATCH*HDIM;               // [S,B,V]
    float* out_ig     = out_logits + (size_t)SEQ*BATCH*VDIM;   // [1,B,H]
    float* out_fg     = out_ig + BATCH*HDIM;                   // [1,B,H]

    float* embeds = sym_addr(g_embeds);
    float* xi     = sym_addr(g_xi);
    float* xf     = sym_addr(g_xf);
    float* seq1   = sym_addr(g_seq1);
    float* seq2   = sym_addr(g_seq2);
    float* lat    = sym_addr(g_lat);      // lat buf 0; buf 1 at +BATCH*HDIM
    float* part   = sym_addr(g_part);
    float* lat0 = lat;
    float* lat1 = lat + BATCH*HDIM;

    // 1) Embedding gather
    gather_kernel<<<MROWS, 256>>>(word, emb, embeds);

    // 2) Layer-1 input gate preactivations: xi/xf = embeds @ W^T + b
    {
        dim3 grid(HDIM/128, MROWS/128);
        sgemm_nt_kernel<<<grid, 256>>>(embeds, Wxi_w, Wxi_b, xi, MROWS, HDIM, EDIM);
        sgemm_nt_kernel<<<grid, 256>>>(embeds, Wxf_w, Wxf_b, xf, MROWS, HDIM, EDIM);
    }

    // 3) Latent init
    copy_kernel<<<(BATCH*HDIM + 255)/256, 256>>>(latent, lat0, BATCH*HDIM);

    // 4) Layer-1 recurrence
    for (int t = 0; t < SEQ; t++) {
        float* lin  = (t & 1) ? lat1 : lat0;
        float* lout = (t & 1) ? lat0 : lat1;
        step_gemm_kernel<<<dim3(16, KSPLIT), 256>>>(lin, Whi, Whf, part);
        step_update_kernel<<<128, 256>>>(part,
            xi + (size_t)t*BATCH*HDIM, xf + (size_t)t*BATCH*HDIM,
            embeds + (size_t)t*BATCH*HDIM,
            lin, lout, seq1 + (size_t)t*BATCH*HDIM,
            nullptr, nullptr, nullptr);
    }
    // after 128 steps, final latent is in lat0

    // 5) Layer-2 input gate preactivations from seq1
    {
        dim3 grid(HDIM/128, MROWS/128);
        sgemm_nt_kernel<<<grid, 256>>>(seq1, Wxi2_w, Wxi2_b, xi, MROWS, HDIM, HDIM);
        sgemm_nt_kernel<<<grid, 256>>>(seq1, Wxf2_w, Wxf2_b, xf, MROWS, HDIM, HDIM);
    }

    // 6) Layer-2 recurrence (continues ping-pong from lat0)
    for (int t = 0; t < SEQ; t++) {
        float* lin  = (t & 1) ? lat1 : lat0;
        float* lout = (t & 1) ? lat0 : lat1;
        bool last = (t == SEQ-1);
        step_gemm_kernel<<<dim3(16, KSPLIT), 256>>>(lin, Whi2, Whf2, part);
        step_update_kernel<<<128, 256>>>(part,
            xi + (size_t)t*BATCH*HDIM, xf + (size_t)t*BATCH*HDIM,
            seq1 + (size_t)t*BATCH*HDIM,
            lin, lout, seq2 + (size_t)t*BATCH*HDIM,
            last ? out_ig : nullptr,
            last ? out_fg : nullptr,
            last ? out_latent : nullptr);
    }

    // 7) Logits: seq2 @ h2o_w^T + h2o_b  -> [S*B, V]
    {
        dim3 grid(VDIM/128, MROWS/128);
        sgemm_nt_kernel<<<grid, 256>>>(seq2, h2o_w, h2o_b, out_logits, MROWS, VDIM, HDIM);
    }
}

// round 9
// speedup vs baseline: 1.0020x; 1.0010x over previous
#include <cuda_runtime.h>
#include <math.h>

// Problem constants
#define SEQ   128
#define BATCH 32
#define HDIM  1024
#define EDIM  1024
#define VDIM  32000
#define MROWS (SEQ*BATCH)   // 4096
#define KSPLIT 8

// ---------------------------------------------------------------------------
// Device scratch (no allocations allowed)
// ---------------------------------------------------------------------------
__device__ float g_embeds[MROWS*EDIM];          // 16 MB  [S,B,E]
__device__ float g_xi[MROWS*HDIM];              // 16 MB  gate-i preacts (per layer, reused)
__device__ float g_xf[MROWS*HDIM];              // 16 MB
__device__ float g_seq1[MROWS*HDIM];            // 16 MB  layer-1 outputs
__device__ float g_seq2[MROWS*HDIM];            // 16 MB  layer-2 outputs
__device__ float g_lat[2][BATCH*HDIM];          // ping-pong latent
__device__ float g_part[KSPLIT*BATCH*2*HDIM];   // split-K partials [ks][b][2048]

// ---------------------------------------------------------------------------
// Embedding gather: out[sb, :] = emb[word[sb], :]
// ---------------------------------------------------------------------------
__global__ void __launch_bounds__(256) gather_kernel(
    const int* __restrict__ word, const float* __restrict__ emb,
    float* __restrict__ out)
{
    int sb = blockIdx.x;                 // 0..4095
    int w = word[sb];
    const float4* src = (const float4*)(emb + (size_t)w * EDIM);
    float4* dst = (float4*)(out + (size_t)sb * EDIM);
    #pragma unroll
    for (int i = threadIdx.x; i < EDIM/4; i += 256)
        dst[i] = src[i];
}

// ---------------------------------------------------------------------------
// Simple copy kernel (latent init)
// ---------------------------------------------------------------------------
__global__ void copy_kernel(const float* __restrict__ src, float* __restrict__ dst, int n)
{
    int i = blockIdx.x * blockDim.x + threadIdx.x;
    if (i < n) dst[i] = src[i];
}

// ---------------------------------------------------------------------------
// SGEMM (NT): C[M,N] = A[M,K] @ B[N,K]^T + bias[N]
// A, B, C row-major. M,N multiples of 128, K multiple of 8, N multiple of 4.
// 128x128 block tile, 8x8 per-thread tile, 256 threads.
// ---------------------------------------------------------------------------
__global__ void __launch_bounds__(256) sgemm_nt_kernel(
    const float* __restrict__ A, const float* __restrict__ B,
    const float* __restrict__ bias, float* __restrict__ C,
    int M, int N, int K)
{
    const int BM = 128, BN = 128, BK = 8;
    __shared__ float As[BK][BM+4];
    __shared__ float Bs[BK][BN+4];

    int tid = threadIdx.x;
    int bm = blockIdx.y * BM;
    int bn = blockIdx.x * BN;
    int tx = tid & 15;       // 0..15 -> n
    int ty = tid >> 4;       // 0..15 -> m

    float acc[8][8];
    #pragma unroll
    for (int i = 0; i < 8; i++)
        #pragma unroll
        for (int j = 0; j < 8; j++) acc[i][j] = 0.f;

    int lrow = tid >> 1;          // 0..127
    int lcol = (tid & 1) * 4;     // 0 or 4
    const float* Ap = A + (size_t)(bm + lrow) * K + lcol;
    const float* Bp = B + (size_t)(bn + lrow) * K + lcol;

    for (int k0 = 0; k0 < K; k0 += BK) {
        float4 av = *(const float4*)(Ap + k0);
        float4 bv = *(const float4*)(Bp + k0);
        As[lcol+0][lrow] = av.x; As[lcol+1][lrow] = av.y;
        As[lcol+2][lrow] = av.z; As[lcol+3][lrow] = av.w;
        Bs[lcol+0][lrow] = bv.x; Bs[lcol+1][lrow] = bv.y;
        Bs[lcol+2][lrow] = bv.z; Bs[lcol+3][lrow] = bv.w;
        __syncthreads();

        #pragma unroll
        for (int k = 0; k < BK; k++) {
            float a[8], b[8];
            *(float4*)&a[0] = *(const float4*)&As[k][ty*8];
            *(float4*)&a[4] = *(const float4*)&As[k][ty*8+4];
            *(float4*)&b[0] = *(const float4*)&Bs[k][tx*8];
            *(float4*)&b[4] = *(const float4*)&Bs[k][tx*8+4];
            #pragma unroll
            for (int i = 0; i < 8; i++)
                #pragma unroll
                for (int j = 0; j < 8; j++)
                    acc[i][j] += a[i] * b[j];
        }
        __syncthreads();
    }

    #pragma unroll
    for (int i = 0; i < 8; i++) {
        size_t row = (size_t)(bm + ty*8 + i);
        #pragma unroll
        for (int j = 0; j < 8; j += 4) {
            int col = bn + tx*8 + j;
            float4 v;
            v.x = acc[i][j+0] + bias[col+0];
            v.y = acc[i][j+1] + bias[col+1];
            v.z = acc[i][j+2] + bias[col+2];
            v.w = acc[i][j+3] + bias[col+3];
            *(float4*)&C[row * (size_t)N + col] = v;
        }
    }
}

// ---------------------------------------------------------------------------
// Recurrence step GEMM (split-K): partial[ks][b][g2] = sum_{k in slice}
//   lat[b,k] * W[g2][k]   where g2<1024 -> Whi row g2, else Whf row g2-1024.
// grid = (16 g-tiles of 128, 8 k-slices of 128), 256 threads.
// Per-thread 4(b) x 4(g) register tile.
// ---------------------------------------------------------------------------
__global__ void __launch_bounds__(256) step_gemm_kernel(
    const float* __restrict__ lat,   // [B,H]
    const float* __restrict__ Wi,    // [H,H]
    const float* __restrict__ Wf,    // [H,H]
    float* __restrict__ part)        // [KSPLIT][B][2H]
{
    __shared__ float lat_s[8][36];   // [k][b], padded (stride 144B, 16B aligned)
    __shared__ float w_s[8][132];    // [k][g], padded (stride 528B, 16B aligned)

    int tid = threadIdx.x;
    int gbase = blockIdx.x * 128;        // 0..2047
    int k0 = blockIdx.y * 128;           // k-slice base

    const float* W = (gbase < HDIM) ? Wi : Wf;
    int grow = (gbase < HDIM) ? gbase : (gbase - HDIM);

    float acc[4][4];
    #pragma unroll
    for (int i = 0; i < 4; i++)
        #pragma unroll
        for (int j = 0; j < 4; j++) acc[i][j] = 0.f;

    int bq = (tid >> 5) * 4;     // batch base (0..28)
    int gq = (tid & 31) * 4;     // g base within tile (0..124)

    for (int kk = 0; kk < 128; kk += 8) {
        // load latent chunk: 32 b x 8 k
        {
            int b = tid >> 3, k = tid & 7;
            lat_s[k][b] = lat[b * HDIM + k0 + kk + k];
        }
        // load W chunk: 128 g x 8 k (float4 over k)
        {
            int g = tid >> 1, kq = (tid & 1) * 4;
            float4 wv = *(const float4*)&W[(size_t)(grow + g) * HDIM + k0 + kk + kq];
            w_s[kq+0][g] = wv.x; w_s[kq+1][g] = wv.y;
            w_s[kq+2][g] = wv.z; w_s[kq+3][g] = wv.w;
        }
        __syncthreads();
        #pragma unroll
        for (int k = 0; k < 8; k++) {
            float a[4], b4[4];
            *(float4*)a  = *(const float4*)&lat_s[k][bq];
            *(float4*)b4 = *(const float4*)&w_s[k][gq];
            #pragma unroll
            for (int i = 0; i < 4; i++)
                #pragma unroll
                for (int j = 0; j < 4; j++)
                    acc[i][j] += a[i] * b4[j];
        }
        __syncthreads();
    }

    float* p = part + (size_t)(blockIdx.y * BATCH) * (2*HDIM);
    #pragma unroll
    for (int i = 0; i < 4; i++) {
        int b = bq + i;
        *(float4*)&p[b * (2*HDIM) + gbase + gq] = *(float4*)acc[i];
    }
}

// ---------------------------------------------------------------------------
// Recurrence step update: reduce split-K partials, sigmoid gates, latent update
// ---------------------------------------------------------------------------
__global__ void __launch_bounds__(256) step_update_kernel(
    const float* __restrict__ part,
    const float* __restrict__ xi_t,  // [B,H]
    const float* __restrict__ xf_t,  // [B,H]
    const float* __restrict__ x_t,   // [B,H]
    const float* __restrict__ lat_in,
    float* __restrict__ lat_out,
    float* __restrict__ seq_out,
    float* __restrict__ ig_out,      // nullable (last step of layer 2)
    float* __restrict__ fg_out,      // nullable
    float* __restrict__ lat_final)   // nullable
{
    int idx = blockIdx.x * blockDim.x + threadIdx.x;   // 0..32767
    int b = idx >> 10;      // /HDIM
    int g = idx & 1023;

    float si = 0.f, sf = 0.f;
    #pragma unroll
    for (int ks = 0; ks < KSPLIT; ks++) {
        const float* p = part + (size_t)(ks * BATCH + b) * (2*HDIM);
        si += p[g];
        sf += p[g + HDIM];
    }
    float ig = 1.f / (1.f + expf(-(si + xi_t[idx])));
    float fg = 1.f / (1.f + expf(-(sf + xf_t[idx])));
    float l = ig * x_t[idx] + fg * lat_in[idx];
    lat_out[idx] = l;
    seq_out[idx] = l;
    if (ig_out) {
        ig_out[idx] = ig;
        fg_out[idx] = fg;
        lat_final[idx] = l;
    }
}

// ---------------------------------------------------------------------------
// Host launcher
// ---------------------------------------------------------------------------
static float* sym_addr(const void* symbol)
{
    void* p = nullptr;
    cudaGetSymbolAddress(&p, symbol);
    return (float*)p;
}

extern "C" void kernel_launch(void* const* d_in, const int* in_sizes, int n_in,
                              void* d_out, int out_size)
{
    const int*   word   = (const int*)  d_in[0];
    const float* latent = (const float*)d_in[1];
    const float* emb    = (const float*)d_in[2];
    const float* h2o_w  = (const float*)d_in[3];
    const float* h2o_b  = (const float*)d_in[4];
    const float* Whi    = (const float*)d_in[5];
    const float* Wxi_w  = (const float*)d_in[6];
    const float* Wxi_b  = (const float*)d_in[7];
    const float* Whf    = (const float*)d_in[8];
    const float* Wxf_w  = (const float*)d_in[9];
    const float* Wxf_b  = (const float*)d_in[10];
    const float* Whi2   = (const float*)d_in[11];
    const float* Wxi2_w = (const float*)d_in[12];
    const float* Wxi2_b = (const float*)d_in[13];
    const float* Whf2   = (const float*)d_in[14];
    const float* Wxf2_w = (const float*)d_in[15];
    const float* Wxf2_b = (const float*)d_in[16];

    float* out_latent = (float*)d_out;                         // [1,B,H]
    float* out_logits = out_latent + BATCH*HDIM;               // [S,B,V]
    float* out_ig     = out_logits + (size_t)SEQ*BATCH*VDIM;   // [1,B,H]
    float* out_fg     = out_ig + BATCH*HDIM;                   // [1,B,H]

    float* embeds = sym_addr(g_embeds);
    float* xi     = sym_addr(g_xi);
    float* xf     = sym_addr(g_xf);
    float* seq1   = sym_addr(g_seq1);
    float* seq2   = sym_addr(g_seq2);
    float* lat    = sym_addr(g_lat);      // lat buf 0; buf 1 at +BATCH*HDIM
    float* part   = sym_addr(g_part);
    float* lat0 = lat;
    float* lat1 = lat + BATCH*HDIM;

    // 1) Embedding gather
    gather_kernel<<<MROWS, 256>>>(word, emb, embeds);

    // 2) Layer-1 input gate preactivations: xi/xf = embeds @ W^T + b
    {
        dim3 grid(HDIM/128, MROWS/128);
        sgemm_nt_kernel<<<grid, 256>>>(embeds, Wxi_w, Wxi_b, xi, MROWS, HDIM, EDIM);
        sgemm_nt_kernel<<<grid, 256>>>(embeds, Wxf_w, Wxf_b, xf, MROWS, HDIM, EDIM);
    }

    // 3) Latent init
    copy_kernel<<<(BATCH*HDIM + 255)/256, 256>>>(latent, lat0, BATCH*HDIM);

    // 4) Layer-1 recurrence
    for (int t = 0; t < SEQ; t++) {
        float* lin  = (t & 1) ? lat1 : lat0;
        float* lout = (t & 1) ? lat0 : lat1;
        step_gemm_kernel<<<dim3(16, KSPLIT), 256>>>(lin, Whi, Whf, part);
        step_update_kernel<<<128, 256>>>(part,
            xi + (size_t)t*BATCH*HDIM, xf + (size_t)t*BATCH*HDIM,
            embeds + (size_t)t*BATCH*HDIM,
            lin, lout, seq1 + (size_t)t*BATCH*HDIM,
            nullptr, nullptr, nullptr);
    }
    // after 128 steps, final latent is in lat0

    // 5) Layer-2 input gate preactivations from seq1
    {
        dim3 grid(HDIM/128, MROWS/128);
        sgemm_nt_kernel<<<grid, 256>>>(seq1, Wxi2_w, Wxi2_b, xi, MROWS, HDIM, HDIM);
        sgemm_nt_kernel<<<grid, 256>>>(seq1, Wxf2_w, Wxf2_b, xf, MROWS, HDIM, HDIM);
    }

    // 6) Layer-2 recurrence (continues ping-pong from lat0)
    for (int t = 0; t < SEQ; t++) {
        float* lin  = (t & 1) ? lat1 : lat0;
        float* lout = (t & 1) ? lat0 : lat1;
        bool last = (t == SEQ-1);
        step_gemm_kernel<<<dim3(16, KSPLIT), 256>>>(lin, Whi2, Whf2, part);
        step_update_kernel<<<128, 256>>>(part,
            xi + (size_t)t*BATCH*HDIM, xf + (size_t)t*BATCH*HDIM,
            seq1 + (size_t)t*BATCH*HDIM,
            lin, lout, seq2 + (size_t)t*BATCH*HDIM,
            last ? out_ig : nullptr,
            last ? out_fg : nullptr,
            last ? out_latent : nullptr);
    }

    // 7) Logits: seq2 @ h2o_w^T + h2o_b  -> [S*B, V]
    {
        dim3 grid(VDIM/128, MROWS/128);
        sgemm_nt_kernel<<<grid, 256>>>(seq2, h2o_w, h2o_b, out_logits, MROWS, VDIM, HDIM);
    }
}